// round 8
// baseline (speedup 1.0000x reference)
#include <cuda_runtime.h>
#include <cstdint>
#include <cstddef>

// Problem constants (fixed by the dataset problem)
#define HDIM   512
#define BATCH  32
#define VOCAB  32000
#define MAXN   64
#define VPB    256                 // vocab rows per logits CTA
#define NCAND  (VOCAB / VPB)       // 125 candidate blocks
#define SOS_TOK 1

// -------- persistent scratch (no allocations allowed) --------
__device__ float g_h0[2][BATCH * HDIM];   // ping-pong hidden, layer 0
__device__ float g_h1[2][BATCH * HDIM];   // ping-pong hidden, layer 1
__device__ float g_cval[NCAND * BATCH];   // per-block argmax value
__device__ int   g_cidx[NCAND * BATCH];   // per-block argmax index

// -------- packed fp32x2 FMA (Blackwell FFMA2; full fp32 per lane) --------
__device__ __forceinline__ float2 ffma2(float2 a, float2 b, float2 c) {
    unsigned long long ua = *reinterpret_cast<unsigned long long*>(&a);
    unsigned long long ub = *reinterpret_cast<unsigned long long*>(&b);
    unsigned long long uc = *reinterpret_cast<unsigned long long*>(&c);
    unsigned long long ud;
    asm("fma.rn.f32x2 %0, %1, %2, %3;" : "=l"(ud) : "l"(ua), "l"(ub), "l"(uc));
    return *reinterpret_cast<float2*>(&ud);
}

// out modes: 0 = int32 tokens only; 1 = float32 tokens then h_t; 2 = float32 h_t only
#define MODE_INT_TOK 0
#define MODE_FLOAT_ALL 1
#define MODE_FLOAT_H 2

// ---------------------------------------------------------------
// init: copy harness h_0 into parity-0 buffers
// ---------------------------------------------------------------
__global__ void init_kernel(const float* __restrict__ h0in) {
    int i = blockIdx.x * blockDim.x + threadIdx.x;
    if (i < BATCH * HDIM) {
        g_h0[0][i] = h0in[i];
        g_h1[0][i] = h0in[BATCH * HDIM + i];
    }
}

// ---------------------------------------------------------------
// GRU layer kernel. grid = (4 j-blocks, 32 batch), 128 threads.
// layer==0: resolves previous step's argmax (from candidates), writes the
//           emitted token of step t-1 to d_out, gathers x = emb[token].
// layer==1: x = freshly written h0 (this step).
// ---------------------------------------------------------------
__global__ __launch_bounds__(128)
void gru_layer(const float* __restrict__ emb,
               const float* __restrict__ Wih, const float* __restrict__ Whh,
               const float* __restrict__ bih, const float* __restrict__ bhh,
               int t, int layer,
               float* __restrict__ dout_f, int* __restrict__ dout_i, int mode)
{
    const int b   = blockIdx.y;
    const int tid = threadIdx.x;
    const int j   = blockIdx.x * 128 + tid;      // 0..511
    const int rp  = t & 1;
    const int wp  = 1 - rp;

    __shared__ float xs[HDIM];
    __shared__ float hs[HDIM];
    __shared__ float sval[128];
    __shared__ int   sidx[128];

    const float* xrow;
    const float* hrow;

    if (layer == 0) {
        int tok;
        if (t == 0) {
            tok = SOS_TOK;
        } else {
            // parallel argmax over 125 candidate blocks, tie -> lowest index
            float v = -3.4e38f; int ix = 0x7fffffff;
            if (tid < NCAND) { v = g_cval[tid * BATCH + b]; ix = g_cidx[tid * BATCH + b]; }
            sval[tid] = v; sidx[tid] = ix;
            __syncthreads();
            #pragma unroll
            for (int s = 64; s > 0; s >>= 1) {
                if (tid < s) {
                    float ov = sval[tid + s]; int oi = sidx[tid + s];
                    if (ov > sval[tid] || (ov == sval[tid] && oi < sidx[tid])) {
                        sval[tid] = ov; sidx[tid] = oi;
                    }
                }
                __syncthreads();
            }
            tok = sidx[0];
            // token emitted at step t-1
            if (blockIdx.x == 0 && tid == 0) {
                if (mode == MODE_INT_TOK)        dout_i[b * MAXN + (t - 1)] = tok;
                else if (mode == MODE_FLOAT_ALL) dout_f[b * MAXN + (t - 1)] = (float)tok;
            }
        }
        xrow = emb + (size_t)tok * HDIM;
        hrow = &g_h0[rp][0] + b * HDIM;
    } else {
        xrow = &g_h0[wp][0] + b * HDIM;   // new h0 written earlier this step
        hrow = &g_h1[rp][0] + b * HDIM;
    }

    // stage x and h rows
    for (int k = tid; k < HDIM; k += 128) { xs[k] = xrow[k]; hs[k] = hrow[k]; }
    __syncthreads();

    // 6 dot products of length 512 (r,z,n against x via Wih; against h via Whh)
    const float4* xs4 = (const float4*)xs;
    const float4* hs4 = (const float4*)hs;
    const float4* Wr = (const float4*)(Wih + (size_t)j * HDIM);
    const float4* Wz = (const float4*)(Wih + (size_t)(j + 512) * HDIM);
    const float4* Wn = (const float4*)(Wih + (size_t)(j + 1024) * HDIM);
    const float4* Ur = (const float4*)(Whh + (size_t)j * HDIM);
    const float4* Uz = (const float4*)(Whh + (size_t)(j + 512) * HDIM);
    const float4* Un = (const float4*)(Whh + (size_t)(j + 1024) * HDIM);

    float2 ar = make_float2(0.f, 0.f), az = ar, an = ar;
    float2 br = ar, bz = ar, bn = ar;

    #pragma unroll 4
    for (int q = 0; q < HDIM / 4; q++) {
        float4 x4 = xs4[q], h4 = hs4[q];
        float2 xlo = make_float2(x4.x, x4.y), xhi = make_float2(x4.z, x4.w);
        float2 hlo = make_float2(h4.x, h4.y), hhi = make_float2(h4.z, h4.w);
        float4 w;
        w = Wr[q]; ar = ffma2(make_float2(w.x, w.y), xlo, ar); ar = ffma2(make_float2(w.z, w.w), xhi, ar);
        w = Wz[q]; az = ffma2(make_float2(w.x, w.y), xlo, az); az = ffma2(make_float2(w.z, w.w), xhi, az);
        w = Wn[q]; an = ffma2(make_float2(w.x, w.y), xlo, an); an = ffma2(make_float2(w.z, w.w), xhi, an);
        w = Ur[q]; br = ffma2(make_float2(w.x, w.y), hlo, br); br = ffma2(make_float2(w.z, w.w), hhi, br);
        w = Uz[q]; bz = ffma2(make_float2(w.x, w.y), hlo, bz); bz = ffma2(make_float2(w.z, w.w), hhi, bz);
        w = Un[q]; bn = ffma2(make_float2(w.x, w.y), hlo, bn); bn = ffma2(make_float2(w.z, w.w), hhi, bn);
    }

    float ir  = ar.x + ar.y + bih[j];
    float iz  = az.x + az.y + bih[512 + j];
    float in_ = an.x + an.y + bih[1024 + j];
    float hr  = br.x + br.y + bhh[j];
    float hz  = bz.x + bz.y + bhh[512 + j];
    float hn  = bn.x + bn.y + bhh[1024 + j];

    // activations in double -> negligible transcendental mismatch vs JAX fp32
    double r = 1.0 / (1.0 + exp(-(double)(ir + hr)));
    double z = 1.0 / (1.0 + exp(-(double)(iz + hz)));
    double n = tanh((double)in_ + r * (double)hn);
    float hout = (float)((1.0 - z) * n + z * (double)hs[j]);

    float* dst = (layer == 0) ? &g_h0[wp][0] : &g_h1[wp][0];
    dst[b * HDIM + j] = hout;
}

// ---------------------------------------------------------------
// logits + per-block argmax. grid = 125 CTAs, 256 threads.
// warp handles 32 vocab rows (lane = row); h1 [32x512] staged in 64KB smem.
// fp32x2 FMA; per-batch warp argmax via shuffles; CTA-level candidate out.
// ---------------------------------------------------------------
__global__ __launch_bounds__(256, 1)
void logits_kernel(const float* __restrict__ Wout, const float* __restrict__ bout, int t)
{
    extern __shared__ float hsm[];            // [BATCH][HDIM] fp32 = 64KB
    const int wp = 1 - (t & 1);

    {
        const float4* src = (const float4*)(&g_h1[wp][0]);
        float4* dst = (float4*)hsm;
        for (int i = threadIdx.x; i < BATCH * HDIM / 4; i += blockDim.x) dst[i] = src[i];
    }
    __syncthreads();

    const int warp = threadIdx.x >> 5;
    const int lane = threadIdx.x & 31;
    const int v    = blockIdx.x * VPB + warp * 32 + lane;

    const float4* Wv  = (const float4*)(Wout + (size_t)v * HDIM);
    const float4* hs4 = (const float4*)hsm;

    float2 acc[BATCH];
    #pragma unroll
    for (int b = 0; b < BATCH; b++) acc[b] = make_float2(0.f, 0.f);

    for (int kc = 0; kc < HDIM / 16; kc++) {     // 32 chunks of 16 K-elems
        float4 w0 = Wv[kc * 4 + 0], w1 = Wv[kc * 4 + 1];
        float4 w2 = Wv[kc * 4 + 2], w3 = Wv[kc * 4 + 3];
        float2 wl0 = make_float2(w0.x, w0.y), wh0 = make_float2(w0.z, w0.w);
        float2 wl1 = make_float2(w1.x, w1.y), wh1 = make_float2(w1.z, w1.w);
        float2 wl2 = make_float2(w2.x, w2.y), wh2 = make_float2(w2.z, w2.w);
        float2 wl3 = make_float2(w3.x, w3.y), wh3 = make_float2(w3.z, w3.w);
        #pragma unroll
        for (int b = 0; b < BATCH; b++) {
            const float4* hb = hs4 + b * (HDIM / 4) + kc * 4;   // uniform -> smem broadcast
            float4 a0 = hb[0], a1 = hb[1], a2 = hb[2], a3 = hb[3];
            float2 s = acc[b];
            s = ffma2(wl0, make_float2(a0.x, a0.y), s);
            s = ffma2(wh0, make_float2(a0.z, a0.w), s);
            s = ffma2(wl1, make_float2(a1.x, a1.y), s);
            s = ffma2(wh1, make_float2(a1.z, a1.w), s);
            s = ffma2(wl2, make_float2(a2.x, a2.y), s);
            s = ffma2(wh2, make_float2(a2.z, a2.w), s);
            s = ffma2(wl3, make_float2(a3.x, a3.y), s);
            s = ffma2(wh3, make_float2(a3.z, a3.w), s);
            acc[b] = s;
        }
    }

    const float bv = bout[v];

    __shared__ float wval[8][BATCH];
    __shared__ int   widx[8][BATCH];

    #pragma unroll
    for (int b = 0; b < BATCH; b++) {
        float val = acc[b].x + acc[b].y + bv;
        int   idx = v;
        #pragma unroll
        for (int m = 16; m > 0; m >>= 1) {
            float ov = __shfl_xor_sync(0xffffffffu, val, m);
            int   oi = __shfl_xor_sync(0xffffffffu, idx, m);
            if (ov > val || (ov == val && oi < idx)) { val = ov; idx = oi; }
        }
        if (lane == 0) { wval[warp][b] = val; widx[warp][b] = idx; }
    }
    __syncthreads();

    if (threadIdx.x < BATCH) {
        int b = threadIdx.x;
        float best = wval[0][b]; int bi = widx[0][b];
        #pragma unroll
        for (int w = 1; w < 8; w++) {
            float ov = wval[w][b]; int oi = widx[w][b];
            if (ov > best || (ov == best && oi < bi)) { best = ov; bi = oi; }
        }
        g_cval[blockIdx.x * BATCH + b] = best;
        g_cidx[blockIdx.x * BATCH + b] = bi;
    }
}

// ---------------------------------------------------------------
// final: resolve token of step 63, emit it, copy h_t. grid = 32 CTAs (one per b).
// ---------------------------------------------------------------
__global__ __launch_bounds__(128)
void final_kernel(float* __restrict__ dout_f, int* __restrict__ dout_i, int mode)
{
    const int b   = blockIdx.x;
    const int tid = threadIdx.x;

    __shared__ float sval[128];
    __shared__ int   sidx[128];

    float v = -3.4e38f; int ix = 0x7fffffff;
    if (tid < NCAND) { v = g_cval[tid * BATCH + b]; ix = g_cidx[tid * BATCH + b]; }
    sval[tid] = v; sidx[tid] = ix;
    __syncthreads();
    #pragma unroll
    for (int s = 64; s > 0; s >>= 1) {
        if (tid < s) {
            float ov = sval[tid + s]; int oi = sidx[tid + s];
            if (ov > sval[tid] || (ov == sval[tid] && oi < sidx[tid])) {
                sval[tid] = ov; sidx[tid] = oi;
            }
        }
        __syncthreads();
    }
    if (tid == 0) {
        if (mode == MODE_INT_TOK)        dout_i[b * MAXN + (MAXN - 1)] = sidx[0];
        else if (mode == MODE_FLOAT_ALL) dout_f[b * MAXN + (MAXN - 1)] = (float)sidx[0];
    }

    // final hidden state lives in parity 0 after 64 steps
    if (mode != MODE_INT_TOK) {
        int off = (mode == MODE_FLOAT_ALL) ? (BATCH * MAXN) : 0;
        for (int k = tid; k < HDIM; k += 128) {
            dout_f[off + b * HDIM + k]                 = g_h0[0][b * HDIM + k];
            dout_f[off + BATCH * HDIM + b * HDIM + k]  = g_h1[0][b * HDIM + k];
        }
    }
}

// ---------------------------------------------------------------
// host entry — graph-capturable: kernel launches only
// ---------------------------------------------------------------
extern "C" void kernel_launch(void* const* d_in, const int* in_sizes, int n_in,
                              void* d_out, int out_size)
{
    const float* h0   = (const float*)d_in[0];
    const float* emb  = (const float*)d_in[1];
    const float* Wih0 = (const float*)d_in[2];
    const float* Whh0 = (const float*)d_in[3];
    const float* bih0 = (const float*)d_in[4];
    const float* bhh0 = (const float*)d_in[5];
    const float* Wih1 = (const float*)d_in[6];
    const float* Whh1 = (const float*)d_in[7];
    const float* bih1 = (const float*)d_in[8];
    const float* bhh1 = (const float*)d_in[9];
    const float* Wout = (const float*)d_in[10];
    const float* bout = (const float*)d_in[11];
    // d_in[12] = max_n (known constant 64)

    int mode;
    if (out_size == BATCH * MAXN)            mode = MODE_INT_TOK;    // toks only, int32
    else if (out_size == 2 * BATCH * HDIM)   mode = MODE_FLOAT_H;    // h_t only
    else                                     mode = MODE_FLOAT_ALL;  // toks(float) + h_t

    float* dof = (float*)d_out;
    int*   doi = (int*)d_out;

    cudaFuncSetAttribute(logits_kernel, cudaFuncAttributeMaxDynamicSharedMemorySize,
                         BATCH * HDIM * (int)sizeof(float));

    init_kernel<<<(BATCH * HDIM + 511) / 512, 512>>>(h0);

    for (int t = 0; t < MAXN; t++) {
        gru_layer<<<dim3(4, BATCH), 128>>>(emb, Wih0, Whh0, bih0, bhh0, t, 0, dof, doi, mode);
        gru_layer<<<dim3(4, BATCH), 128>>>(emb, Wih1, Whh1, bih1, bhh1, t, 1, dof, doi, mode);
        logits_kernel<<<NCAND, 256, BATCH * HDIM * sizeof(float)>>>(Wout, bout, t);
    }

    final_kernel<<<BATCH, 128>>>(dof, doi, mode);
}

// round 9
// speedup vs baseline: 1.4643x; 1.4643x over previous
#include <cuda_runtime.h>
#include <cstdint>
#include <cstddef>

// Problem constants
#define HDIM   512
#define BATCH  32
#define VOCAB  32000
#define MAXN   64
#define LROWS  256                 // vocab rows per logits CTA
#define NCAND  (VOCAB / LROWS)     // 125 candidate blocks
#define SOS_TOK 1

#define GROWS  3072                // 2*3*HDIM gate rows (x-side 0..1535, h-side 1536..3071)
#define KSPLIT 4
#define KSL    (HDIM / KSPLIT)     // 128 k per split

// -------- persistent scratch (no allocations allowed) --------
__device__ float g_h0[2][BATCH * HDIM];
__device__ float g_h1[2][BATCH * HDIM];
__device__ float g_part[KSPLIT * BATCH * GROWS];   // partial gate sums [kp][b][row]
__device__ float g_cval[NCAND * BATCH];
__device__ int   g_cidx[NCAND * BATCH];
__device__ int   g_tok[BATCH];
__device__ unsigned int g_ctr;

// -------- packed fp32x2 FMA (two independent fp32 FMAs per instr) --------
__device__ __forceinline__ float2 ffma2(float2 a, float2 b, float2 c) {
    unsigned long long ua = *reinterpret_cast<unsigned long long*>(&a);
    unsigned long long ub = *reinterpret_cast<unsigned long long*>(&b);
    unsigned long long uc = *reinterpret_cast<unsigned long long*>(&c);
    unsigned long long ud;
    asm("fma.rn.f32x2 %0, %1, %2, %3;" : "=l"(ud) : "l"(ua), "l"(ub), "l"(uc));
    return *reinterpret_cast<float2*>(&ud);
}

#define MODE_INT_TOK   0
#define MODE_FLOAT_ALL 1
#define MODE_FLOAT_H   2

// ---------------------------------------------------------------
__global__ void init_kernel(const float* __restrict__ h0in) {
    int i = blockIdx.x * blockDim.x + threadIdx.x;
    if (i == 0) g_ctr = 0;
    if (i < BATCH * HDIM) {
        g_h0[0][i] = h0in[i];
        g_h1[0][i] = h0in[BATCH * HDIM + i];
    }
}

// ---------------------------------------------------------------
// Gates GEMM: grid (24 rowblocks, 4 ksplits), 128 threads.
// thread = one gate row; accumulates over all 32 batches for its k-slice.
// Rows 0..1535: Wih @ x ; rows 1536..3071: Whh @ h.
// ---------------------------------------------------------------
__global__ __launch_bounds__(128)
void gates_kernel(const float* __restrict__ Wih, const float* __restrict__ Whh,
                  const float* __restrict__ emb, int t, int layer)
{
    const int rb  = blockIdx.x;          // 0..23
    const int kp  = blockIdx.y;          // 0..3
    const int tid = threadIdx.x;
    const int rglob = rb * 128 + tid;    // 0..3071
    const bool xside = (rb < 12);
    const int wrow = xside ? rglob : (rglob - 1536);
    const int rp = t & 1, wp = 1 - rp;

    const float* W = (xside ? Wih : Whh) + (size_t)wrow * HDIM + kp * KSL;

    __shared__ float xs[BATCH * KSL];   // [b][128]
    __shared__ float hs[BATCH * KSL];

    // stage x slice
    if (layer == 0) {
        for (int i = tid; i < BATCH * (KSL / 4); i += 128) {
            int b = i / (KSL / 4), f = i % (KSL / 4);
            int tok = (t == 0) ? SOS_TOK : g_tok[b];
            ((float4*)xs)[b * (KSL / 4) + f] =
                ((const float4*)(emb + (size_t)tok * HDIM + kp * KSL))[f];
        }
    } else {
        for (int i = tid; i < BATCH * (KSL / 4); i += 128) {
            int b = i / (KSL / 4), f = i % (KSL / 4);
            ((float4*)xs)[b * (KSL / 4) + f] =
                ((const float4*)(&g_h0[wp][0] + b * HDIM + kp * KSL))[f];
        }
    }
    // stage h slice
    {
        const float* hsrc = (layer == 0) ? &g_h0[rp][0] : &g_h1[rp][0];
        for (int i = tid; i < BATCH * (KSL / 4); i += 128) {
            int b = i / (KSL / 4), f = i % (KSL / 4);
            ((float4*)hs)[b * (KSL / 4) + f] =
                ((const float4*)(hsrc + b * HDIM + kp * KSL))[f];
        }
    }
    __syncthreads();

    const float4* src4 = (const float4*)(xside ? xs : hs);
    const float4* W4   = (const float4*)W;

    float2 acc[BATCH];
    #pragma unroll
    for (int b = 0; b < BATCH; b++) acc[b] = make_float2(0.f, 0.f);

    for (int c = 0; c < KSL / 16; c++) {       // 8 chunks of 16 k
        float4 w0 = W4[c * 4 + 0], w1 = W4[c * 4 + 1];
        float4 w2 = W4[c * 4 + 2], w3 = W4[c * 4 + 3];
        float2 wl0 = make_float2(w0.x, w0.y), wh0 = make_float2(w0.z, w0.w);
        float2 wl1 = make_float2(w1.x, w1.y), wh1 = make_float2(w1.z, w1.w);
        float2 wl2 = make_float2(w2.x, w2.y), wh2 = make_float2(w2.z, w2.w);
        float2 wl3 = make_float2(w3.x, w3.y), wh3 = make_float2(w3.z, w3.w);
        #pragma unroll
        for (int b = 0; b < BATCH; b++) {
            const float4* hb = src4 + b * (KSL / 4) + c * 4;   // broadcast
            float4 a0 = hb[0], a1 = hb[1], a2 = hb[2], a3 = hb[3];
            float2 s = acc[b];
            s = ffma2(wl0, make_float2(a0.x, a0.y), s);
            s = ffma2(wh0, make_float2(a0.z, a0.w), s);
            s = ffma2(wl1, make_float2(a1.x, a1.y), s);
            s = ffma2(wh1, make_float2(a1.z, a1.w), s);
            s = ffma2(wl2, make_float2(a2.x, a2.y), s);
            s = ffma2(wh2, make_float2(a2.z, a2.w), s);
            s = ffma2(wl3, make_float2(a3.x, a3.y), s);
            s = ffma2(wh3, make_float2(a3.z, a3.w), s);
            acc[b] = s;
        }
    }

    // P[kp][b][row] — coalesced across threads (row = tid)
    #pragma unroll
    for (int b = 0; b < BATCH; b++)
        g_part[(size_t)(kp * BATCH + b) * GROWS + rglob] = acc[b].x + acc[b].y;
}

// ---------------------------------------------------------------
// Activation: grid 32 (b), 512 threads (j). Sums K-partials, GRU blend.
// ---------------------------------------------------------------
__global__ __launch_bounds__(512)
void act_kernel(const float* __restrict__ bih, const float* __restrict__ bhh,
                int t, int layer)
{
    const int b = blockIdx.x;
    const int j = threadIdx.x;
    const int rp = t & 1, wp = 1 - rp;

    float gir = 0.f, giz = 0.f, gin = 0.f, ghr = 0.f, ghz = 0.f, ghn = 0.f;
    #pragma unroll
    for (int kp = 0; kp < KSPLIT; kp++) {
        const float* P = g_part + (size_t)(kp * BATCH + b) * GROWS;
        gir += P[j];          giz += P[j + 512];  gin += P[j + 1024];
        ghr += P[1536 + j];   ghz += P[2048 + j]; ghn += P[2560 + j];
    }
    gir += bih[j]; giz += bih[512 + j]; gin += bih[1024 + j];
    ghr += bhh[j]; ghz += bhh[512 + j]; ghn += bhh[1024 + j];

    float* hbufs = (layer == 0) ? &g_h0[0][0] : &g_h1[0][0];
    float hprev = hbufs[rp * BATCH * HDIM + b * HDIM + j];

    double r = 1.0 / (1.0 + exp(-(double)(gir + ghr)));
    double z = 1.0 / (1.0 + exp(-(double)(giz + ghz)));
    double n = tanh((double)gin + r * (double)ghn);
    hbufs[wp * BATCH * HDIM + b * HDIM + j] = (float)((1.0 - z) * n + z * (double)hprev);
}

// ---------------------------------------------------------------
// Logits + block argmax + last-CTA global argmax (token resolve).
// grid 125, 256 threads, thread = vocab row. W staged coalesced into smem
// (double-buffered, stride-33 padded -> conflict-free per-lane reads).
// ---------------------------------------------------------------
#define WT_STRIDE 33
#define WT_FLOATS (LROWS * WT_STRIDE)            // 8448
#define HS_FLOATS (BATCH * HDIM)                 // 16384
#define SMEM_LOGITS ((HS_FLOATS + 2 * WT_FLOATS) * 4)

__device__ __forceinline__ void stage_w(const float* __restrict__ Wout, int v0,
                                        int c, float* wb, int tid)
{
    const int rr = tid >> 3;        // 0..31
    const int pp = tid & 7;         // 0..7  (float4 index within 32-k slice)
    #pragma unroll
    for (int pass = 0; pass < 8; pass++) {
        int row = pass * 32 + rr;
        float4 w = *(const float4*)(Wout + (size_t)(v0 + row) * HDIM + c * 32 + pp * 4);
        float* d = wb + row * WT_STRIDE + pp * 4;
        d[0] = w.x; d[1] = w.y; d[2] = w.z; d[3] = w.w;
    }
}

__global__ __launch_bounds__(256, 1)
void logits_kernel(const float* __restrict__ Wout, const float* __restrict__ bout,
                   int t, float* __restrict__ dout_f, int* __restrict__ dout_i, int mode)
{
    extern __shared__ float sm[];
    float* hsm = sm;
    float* wt0 = sm + HS_FLOATS;
    float* wt1 = wt0 + WT_FLOATS;

    const int tid = threadIdx.x;
    const int wp = 1 - (t & 1);
    const int v0 = blockIdx.x * LROWS;

    // stage h1 [32][512]
    {
        const float4* src = (const float4*)(&g_h1[wp][0]);
        for (int i = tid; i < HS_FLOATS / 4; i += 256) ((float4*)hsm)[i] = src[i];
    }
    stage_w(Wout, v0, 0, wt0, tid);
    __syncthreads();

    float2 acc[BATCH];
    #pragma unroll
    for (int b = 0; b < BATCH; b++) acc[b] = make_float2(0.f, 0.f);

    for (int c = 0; c < HDIM / 32; c++) {         // 16 chunks of 32 k
        float* wcur = (c & 1) ? wt1 : wt0;
        if (c + 1 < HDIM / 32) {
            float* wnxt = ((c + 1) & 1) ? wt1 : wt0;
            stage_w(Wout, v0, c + 1, wnxt, tid);
        }
        // load this row's 32 W values (conflict-free: stride 33)
        float wreg[32];
        #pragma unroll
        for (int k = 0; k < 32; k++) wreg[k] = wcur[tid * WT_STRIDE + k];

        #pragma unroll
        for (int b = 0; b < BATCH; b++) {
            const float4* hb = (const float4*)(hsm + b * HDIM + c * 32);  // broadcast
            float2 s = acc[b];
            #pragma unroll
            for (int q = 0; q < 8; q++) {
                float4 a = hb[q];
                s = ffma2(make_float2(wreg[q * 4 + 0], wreg[q * 4 + 1]),
                          make_float2(a.x, a.y), s);
                s = ffma2(make_float2(wreg[q * 4 + 2], wreg[q * 4 + 3]),
                          make_float2(a.z, a.w), s);
            }
            acc[b] = s;
        }
        __syncthreads();
    }

    const float bv = bout[v0 + tid];
    const int warp = tid >> 5;
    const int lane = tid & 31;

    __shared__ float wval[8][BATCH];
    __shared__ int   widx[8][BATCH];

    #pragma unroll
    for (int b = 0; b < BATCH; b++) {
        float val = acc[b].x + acc[b].y + bv;
        int   idx = v0 + tid;
        #pragma unroll
        for (int m = 16; m > 0; m >>= 1) {
            float ov = __shfl_xor_sync(0xffffffffu, val, m);
            int   oi = __shfl_xor_sync(0xffffffffu, idx, m);
            if (ov > val || (ov == val && oi < idx)) { val = ov; idx = oi; }
        }
        if (lane == 0) { wval[warp][b] = val; widx[warp][b] = idx; }
    }
    __syncthreads();

    if (tid < BATCH) {
        int b = tid;
        float best = wval[0][b]; int bi = widx[0][b];
        #pragma unroll
        for (int w = 1; w < 8; w++) {
            float ov = wval[w][b]; int oi = widx[w][b];
            if (ov > best || (ov == best && oi < bi)) { best = ov; bi = oi; }
        }
        g_cval[blockIdx.x * BATCH + b] = best;
        g_cidx[blockIdx.x * BATCH + b] = bi;
    }

    // ---- last-CTA global argmax: resolve + emit token t ----
    __threadfence();
    __syncthreads();
    __shared__ int islast;
    if (tid == 0) {
        unsigned int o = atomicAdd(&g_ctr, 1u);
        islast = (o == NCAND - 1) ? 1 : 0;
    }
    __syncthreads();
    if (islast) {
        __threadfence();
        if (tid < BATCH) {
            int b = tid;
            float best = -3.4e38f; int bi = 0x7fffffff;
            for (int cnd = 0; cnd < NCAND; cnd++) {
                float ov = g_cval[cnd * BATCH + b];
                int   oi = g_cidx[cnd * BATCH + b];
                if (ov > best || (ov == best && oi < bi)) { best = ov; bi = oi; }
            }
            g_tok[b] = bi;
            if (mode == MODE_INT_TOK)        dout_i[b * MAXN + t] = bi;
            else if (mode == MODE_FLOAT_ALL) dout_f[b * MAXN + t] = (float)bi;
        }
        if (tid == 0) g_ctr = 0;
    }
}

// ---------------------------------------------------------------
// final: copy h_t (parity 0 after 64 steps). grid 32, 128 threads.
// ---------------------------------------------------------------
__global__ __launch_bounds__(128)
void final_kernel(float* __restrict__ dout_f, int mode)
{
    if (mode == MODE_INT_TOK) return;
    const int b = blockIdx.x;
    const int off = (mode == MODE_FLOAT_ALL) ? (BATCH * MAXN) : 0;
    for (int k = threadIdx.x; k < HDIM; k += 128) {
        dout_f[off + b * HDIM + k]                = g_h0[0][b * HDIM + k];
        dout_f[off + BATCH * HDIM + b * HDIM + k] = g_h1[0][b * HDIM + k];
    }
}

// ---------------------------------------------------------------
extern "C" void kernel_launch(void* const* d_in, const int* in_sizes, int n_in,
                              void* d_out, int out_size)
{
    const float* h0   = (const float*)d_in[0];
    const float* emb  = (const float*)d_in[1];
    const float* Wih0 = (const float*)d_in[2];
    const float* Whh0 = (const float*)d_in[3];
    const float* bih0 = (const float*)d_in[4];
    const float* bhh0 = (const float*)d_in[5];
    const float* Wih1 = (const float*)d_in[6];
    const float* Whh1 = (const float*)d_in[7];
    const float* bih1 = (const float*)d_in[8];
    const float* bhh1 = (const float*)d_in[9];
    const float* Wout = (const float*)d_in[10];
    const float* bout = (const float*)d_in[11];

    int mode;
    if (out_size == BATCH * MAXN)          mode = MODE_INT_TOK;
    else if (out_size == 2 * BATCH * HDIM) mode = MODE_FLOAT_H;
    else                                   mode = MODE_FLOAT_ALL;

    float* dof = (float*)d_out;
    int*   doi = (int*)d_out;

    cudaFuncSetAttribute(logits_kernel, cudaFuncAttributeMaxDynamicSharedMemorySize,
                         SMEM_LOGITS);

    init_kernel<<<(BATCH * HDIM + 511) / 512, 512>>>(h0);

    for (int t = 0; t < MAXN; t++) {
        gates_kernel<<<dim3(24, KSPLIT), 128>>>(Wih0, Whh0, emb, t, 0);
        act_kernel<<<BATCH, HDIM>>>(bih0, bhh0, t, 0);
        gates_kernel<<<dim3(24, KSPLIT), 128>>>(Wih1, Whh1, emb, t, 1);
        act_kernel<<<BATCH, HDIM>>>(bih1, bhh1, t, 1);
        logits_kernel<<<NCAND, 256, SMEM_LOGITS>>>(Wout, bout, t, dof, doi, mode);
    }

    final_kernel<<<BATCH, 128>>>(dof, mode);
}

// round 10
// speedup vs baseline: 2.0789x; 1.4197x over previous
#include <cuda_runtime.h>
#include <cstdint>
#include <cstddef>

// Problem constants
#define HDIM   512
#define BATCH  32
#define VOCAB  32000
#define MAXN   64
#define SOS_TOK 1

#define GRID   128                 // persistent CTAs (all resident on 148 SMs)
#define NTHR   256

// logits tiling
#define LROWS  256
#define NCAND  (VOCAB / LROWS)     // 125
// gates tiling
#define GROWS  3072                // 2*3*HDIM gate rows (x-side 0..1535, h-side 1536..3071)
#define KSPLIT 8
#define KSL    (HDIM / KSPLIT)     // 64
#define GATE_CTAS (GROWS / NTHR * KSPLIT)   // 12 * 8 = 96

// -------- persistent scratch --------
__device__ float g_h0[2][BATCH * HDIM];
__device__ float g_h1[2][BATCH * HDIM];
__device__ float g_part[KSPLIT * BATCH * GROWS];
__device__ float g_cval[NCAND * BATCH];
__device__ int   g_cidx[NCAND * BATCH];
__device__ volatile unsigned g_bar_count;

// -------- packed fp32x2 FMA --------
__device__ __forceinline__ float2 ffma2(float2 a, float2 b, float2 c) {
    unsigned long long ua = *reinterpret_cast<unsigned long long*>(&a);
    unsigned long long ub = *reinterpret_cast<unsigned long long*>(&b);
    unsigned long long uc = *reinterpret_cast<unsigned long long*>(&c);
    unsigned long long ud;
    asm("fma.rn.f32x2 %0, %1, %2, %3;" : "=l"(ud) : "l"(ua), "l"(ub), "l"(uc));
    return *reinterpret_cast<float2*>(&ud);
}

#define MODE_INT_TOK   0
#define MODE_FLOAT_ALL 1
#define MODE_FLOAT_H   2

// -------- grid barrier: monotonic counter, per-CTA epoch --------
__device__ __forceinline__ void gbar(unsigned& epoch) {
    __threadfence();
    __syncthreads();
    if (threadIdx.x == 0) {
        epoch += 1;
        unsigned target = epoch * (unsigned)GRID;
        atomicAdd((unsigned*)&g_bar_count, 1u);
        while (g_bar_count < target) { }
        __threadfence();
    }
    __syncthreads();
}

// ---------------------------------------------------------------
__global__ void reset_kernel(const float* __restrict__ h0in) {
    int i = blockIdx.x * blockDim.x + threadIdx.x;
    if (i == 0) g_bar_count = 0;
    if (i < BATCH * HDIM) {
        g_h0[0][i] = h0in[i];
        g_h1[0][i] = h0in[BATCH * HDIM + i];
    }
}

// -------- smem layout (dynamic, reused per phase) --------
#define WT_STRIDE 33
#define WT_FLOATS (LROWS * WT_STRIDE)            // 8448
#define HS_FLOATS (BATCH * HDIM)                 // 16384
#define SMEM_BYTES ((HS_FLOATS + 2 * WT_FLOATS) * 4)   // 133120

__device__ __forceinline__ void stage_w(const float* __restrict__ Wout, int v0,
                                        int c, float* wb, int tid)
{
    const int rr = tid >> 3;
    const int pp = tid & 7;
    #pragma unroll
    for (int pass = 0; pass < 8; pass++) {
        int row = pass * 32 + rr;
        float4 w = *(const float4*)(Wout + (size_t)(v0 + row) * HDIM + c * 32 + pp * 4);
        float* d = wb + row * WT_STRIDE + pp * 4;
        d[0] = w.x; d[1] = w.y; d[2] = w.z; d[3] = w.w;
    }
}

// ---------------------------------------------------------------
__global__ __launch_bounds__(NTHR, 1)
void decoder_kernel(const float* __restrict__ emb,
                    const float* __restrict__ Wih0, const float* __restrict__ Whh0,
                    const float* __restrict__ bih0, const float* __restrict__ bhh0,
                    const float* __restrict__ Wih1, const float* __restrict__ Whh1,
                    const float* __restrict__ bih1, const float* __restrict__ bhh1,
                    const float* __restrict__ Wout, const float* __restrict__ bout,
                    float* __restrict__ dout_f, int* __restrict__ dout_i, int mode)
{
    extern __shared__ float sm[];
    float* hsm = sm;                         // logits: h1 [32][512]
    float* wt0 = sm + HS_FLOATS;
    float* wt1 = wt0 + WT_FLOATS;
    float* xs  = sm;                         // gates: x slice [32][64]
    float* hs  = sm + BATCH * KSL;           // gates: h slice [32][64]

    __shared__ float rv[NTHR];
    __shared__ int   ri[NTHR];
    __shared__ int   stok[BATCH];
    __shared__ float wval[8][BATCH];
    __shared__ int   widx[8][BATCH];

    const int cta = blockIdx.x;
    const int tid = threadIdx.x;
    unsigned epoch = 0;

    for (int t = 0; t < MAXN; t++) {
        const int rp = t & 1, wp = 1 - rp;

        // ================= token resolve (per-CTA, redundant) =================
        if (t == 0) {
            if (tid < BATCH) stok[tid] = SOS_TOK;
            __syncthreads();
        } else {
            const int b = tid >> 3, c8 = tid & 7;
            float best = -3.4e38f; int bi = 0x7fffffff;
            for (int cnd = c8; cnd < NCAND; cnd += 8) {
                float v  = __ldcg(&g_cval[cnd * BATCH + b]);
                int   ix = __ldcg(&g_cidx[cnd * BATCH + b]);
                if (v > best || (v == best && ix < bi)) { best = v; bi = ix; }
            }
            rv[tid] = best; ri[tid] = bi;
            __syncthreads();
            if (c8 == 0) {
                #pragma unroll
                for (int w = 1; w < 8; w++) {
                    float ov = rv[tid + w]; int oi = ri[tid + w];
                    if (ov > best || (ov == best && oi < bi)) { best = ov; bi = oi; }
                }
                stok[b] = bi;
                if (cta == 0) {     // emit token t-1
                    if (mode == MODE_INT_TOK)        dout_i[b * MAXN + (t - 1)] = bi;
                    else if (mode == MODE_FLOAT_ALL) dout_f[b * MAXN + (t - 1)] = (float)bi;
                }
            }
            __syncthreads();
        }

        // ================= two GRU layers =================
        #pragma unroll 1
        for (int layer = 0; layer < 2; layer++) {
            const float* Wih = layer ? Wih1 : Wih0;
            const float* Whh = layer ? Whh1 : Whh0;

            if (cta < GATE_CTAS) {
                const int ks  = cta / 12;
                const int row = (cta % 12) * NTHR + tid;     // 0..3071
                const bool xside = (row < 1536);
                const int wrow = xside ? row : (row - 1536);

                // stage x and h K-slices [32][64]
                for (int i = tid; i < BATCH * (KSL / 4); i += NTHR) {
                    int b = i / (KSL / 4), f = i % (KSL / 4);
                    float4 xv;
                    if (layer == 0)
                        xv = *(const float4*)(emb + (size_t)stok[b] * HDIM + ks * KSL + f * 4);
                    else
                        xv = __ldcg((const float4*)(&g_h0[wp][0] + b * HDIM + ks * KSL + f * 4));
                    ((float4*)xs)[b * (KSL / 4) + f] = xv;
                    const float* hsrc = layer ? &g_h1[rp][0] : &g_h0[rp][0];
                    ((float4*)hs)[b * (KSL / 4) + f] =
                        __ldcg((const float4*)(hsrc + b * HDIM + ks * KSL + f * 4));
                }
                __syncthreads();

                const float4* W4   = (const float4*)((xside ? Wih : Whh) +
                                      (size_t)wrow * HDIM + ks * KSL);
                const float4* src4 = (const float4*)(xside ? xs : hs);

                float2 acc[BATCH];
                #pragma unroll
                for (int b = 0; b < BATCH; b++) acc[b] = make_float2(0.f, 0.f);

                #pragma unroll
                for (int c = 0; c < KSL / 16; c++) {
                    float4 w0 = W4[c * 4 + 0], w1 = W4[c * 4 + 1];
                    float4 w2 = W4[c * 4 + 2], w3 = W4[c * 4 + 3];
                    float2 wl0 = make_float2(w0.x, w0.y), wh0 = make_float2(w0.z, w0.w);
                    float2 wl1 = make_float2(w1.x, w1.y), wh1 = make_float2(w1.z, w1.w);
                    float2 wl2 = make_float2(w2.x, w2.y), wh2 = make_float2(w2.z, w2.w);
                    float2 wl3 = make_float2(w3.x, w3.y), wh3 = make_float2(w3.z, w3.w);
                    #pragma unroll
                    for (int b = 0; b < BATCH; b++) {
                        const float4* hb = src4 + b * (KSL / 4) + c * 4;
                        float4 a0 = hb[0], a1 = hb[1], a2 = hb[2], a3 = hb[3];
                        float2 s = acc[b];
                        s = ffma2(wl0, make_float2(a0.x, a0.y), s);
                        s = ffma2(wh0, make_float2(a0.z, a0.w), s);
                        s = ffma2(wl1, make_float2(a1.x, a1.y), s);
                        s = ffma2(wh1, make_float2(a1.z, a1.w), s);
                        s = ffma2(wl2, make_float2(a2.x, a2.y), s);
                        s = ffma2(wh2, make_float2(a2.z, a2.w), s);
                        s = ffma2(wl3, make_float2(a3.x, a3.y), s);
                        s = ffma2(wh3, make_float2(a3.z, a3.w), s);
                        acc[b] = s;
                    }
                }

                #pragma unroll
                for (int b = 0; b < BATCH; b++)
                    __stcg(&g_part[(size_t)(ks * BATCH + b) * GROWS + row],
                           acc[b].x + acc[b].y);
            }
            gbar(epoch);

            // -------- activation --------
            {
                const int gt = cta * NTHR + tid;
                if (gt < BATCH * HDIM) {
                    const int b = gt >> 9, j = gt & 511;
                    const float* bih = layer ? bih1 : bih0;
                    const float* bhh = layer ? bhh1 : bhh0;

                    float gir = 0.f, giz = 0.f, gin = 0.f, ghr = 0.f, ghz = 0.f, ghn = 0.f;
                    #pragma unroll
                    for (int kp = 0; kp < KSPLIT; kp++) {
                        const float* P = g_part + (size_t)(kp * BATCH + b) * GROWS;
                        gir += __ldcg(&P[j]);          giz += __ldcg(&P[j + 512]);
                        gin += __ldcg(&P[j + 1024]);   ghr += __ldcg(&P[1536 + j]);
                        ghz += __ldcg(&P[2048 + j]);   ghn += __ldcg(&P[2560 + j]);
                    }
                    gir += bih[j]; giz += bih[512 + j]; gin += bih[1024 + j];
                    ghr += bhh[j]; ghz += bhh[512 + j]; ghn += bhh[1024 + j];

                    float* hbuf = layer ? &g_h1[0][0] : &g_h0[0][0];
                    float hprev = __ldcg(&hbuf[rp * BATCH * HDIM + b * HDIM + j]);

                    double r = 1.0 / (1.0 + exp(-(double)(gir + ghr)));
                    double z = 1.0 / (1.0 + exp(-(double)(giz + ghz)));
                    double n = tanh((double)gin + r * (double)ghn);
                    __stcg(&hbuf[wp * BATCH * HDIM + b * HDIM + j],
                           (float)((1.0 - z) * n + z * (double)hprev));
                }
            }
            gbar(epoch);
        }

        // ================= logits + per-CTA candidates =================
        if (cta < NCAND) {
            const int v0 = cta * LROWS;

            {
                const float4* src = (const float4*)(&g_h1[wp][0]);
                for (int i = tid; i < HS_FLOATS / 4; i += NTHR)
                    ((float4*)hsm)[i] = __ldcg(&src[i]);
            }
            stage_w(Wout, v0, 0, wt0, tid);
            __syncthreads();

            float2 acc[BATCH];
            #pragma unroll
            for (int b = 0; b < BATCH; b++) acc[b] = make_float2(0.f, 0.f);

            for (int c = 0; c < HDIM / 32; c++) {
                float* wcur = (c & 1) ? wt1 : wt0;
                if (c + 1 < HDIM / 32) {
                    float* wnxt = ((c + 1) & 1) ? wt1 : wt0;
                    stage_w(Wout, v0, c + 1, wnxt, tid);
                }
                float wreg[32];
                #pragma unroll
                for (int k = 0; k < 32; k++) wreg[k] = wcur[tid * WT_STRIDE + k];

                #pragma unroll
                for (int b = 0; b < BATCH; b++) {
                    const float4* hb = (const float4*)(hsm + b * HDIM + c * 32);
                    float2 s = acc[b];
                    #pragma unroll
                    for (int q = 0; q < 8; q++) {
                        float4 a = hb[q];
                        s = ffma2(make_float2(wreg[q * 4 + 0], wreg[q * 4 + 1]),
                                  make_float2(a.x, a.y), s);
                        s = ffma2(make_float2(wreg[q * 4 + 2], wreg[q * 4 + 3]),
                                  make_float2(a.z, a.w), s);
                    }
                    acc[b] = s;
                }
                __syncthreads();
            }

            const float bv = bout[v0 + tid];
            const int warp = tid >> 5, lane = tid & 31;

            #pragma unroll
            for (int b = 0; b < BATCH; b++) {
                float val = acc[b].x + acc[b].y + bv;
                int   idx = v0 + tid;
                #pragma unroll
                for (int m = 16; m > 0; m >>= 1) {
                    float ov = __shfl_xor_sync(0xffffffffu, val, m);
                    int   oi = __shfl_xor_sync(0xffffffffu, idx, m);
                    if (ov > val || (ov == val && oi < idx)) { val = ov; idx = oi; }
                }
                if (lane == 0) { wval[warp][b] = val; widx[warp][b] = idx; }
            }
            __syncthreads();

            if (tid < BATCH) {
                int b = tid;
                float best = wval[0][b]; int bi = widx[0][b];
                #pragma unroll
                for (int w = 1; w < 8; w++) {
                    float ov = wval[w][b]; int oi = widx[w][b];
                    if (ov > best || (ov == best && oi < bi)) { best = ov; bi = oi; }
                }
                __stcg(&g_cval[cta * BATCH + b], best);
                __stcg(&g_cidx[cta * BATCH + b], bi);
            }
        }
        gbar(epoch);
    }

    // ================= epilogue: token 63 + h_t =================
    if (cta == 0) {
        const int b = tid >> 3, c8 = tid & 7;
        float best = -3.4e38f; int bi = 0x7fffffff;
        for (int cnd = c8; cnd < NCAND; cnd += 8) {
            float v  = __ldcg(&g_cval[cnd * BATCH + b]);
            int   ix = __ldcg(&g_cidx[cnd * BATCH + b]);
            if (v > best || (v == best && ix < bi)) { best = v; bi = ix; }
        }
        rv[tid] = best; ri[tid] = bi;
        __syncthreads();
        if (c8 == 0) {
            #pragma unroll
            for (int w = 1; w < 8; w++) {
                float ov = rv[tid + w]; int oi = ri[tid + w];
                if (ov > best || (ov == best && oi < bi)) { best = ov; bi = oi; }
            }
            if (mode == MODE_INT_TOK)        dout_i[b * MAXN + (MAXN - 1)] = bi;
            else if (mode == MODE_FLOAT_ALL) dout_f[b * MAXN + (MAXN - 1)] = (float)bi;
        }
    }
    if (mode != MODE_INT_TOK && cta >= 1 && cta <= BATCH) {
        const int b = cta - 1;
        const int off = (mode == MODE_FLOAT_ALL) ? (BATCH * MAXN) : 0;
        for (int k = tid; k < HDIM; k += NTHR) {
            dout_f[off + b * HDIM + k]                = __ldcg(&g_h0[0][b * HDIM + k]);
            dout_f[off + BATCH * HDIM + b * HDIM + k] = __ldcg(&g_h1[0][b * HDIM + k]);
        }
    }
}

// ---------------------------------------------------------------
extern "C" void kernel_launch(void* const* d_in, const int* in_sizes, int n_in,
                              void* d_out, int out_size)
{
    const float* h0   = (const float*)d_in[0];
    const float* emb  = (const float*)d_in[1];
    const float* Wih0 = (const float*)d_in[2];
    const float* Whh0 = (const float*)d_in[3];
    const float* bih0 = (const float*)d_in[4];
    const float* bhh0 = (const float*)d_in[5];
    const float* Wih1 = (const float*)d_in[6];
    const float* Whh1 = (const float*)d_in[7];
    const float* bih1 = (const float*)d_in[8];
    const float* bhh1 = (const float*)d_in[9];
    const float* Wout = (const float*)d_in[10];
    const float* bout = (const float*)d_in[11];

    int mode;
    if (out_size == BATCH * MAXN)          mode = MODE_INT_TOK;
    else if (out_size == 2 * BATCH * HDIM) mode = MODE_FLOAT_H;
    else                                   mode = MODE_FLOAT_ALL;

    float* dof = (float*)d_out;
    int*   doi = (int*)d_out;

    cudaFuncSetAttribute(decoder_kernel, cudaFuncAttributeMaxDynamicSharedMemorySize,
                         SMEM_BYTES);

    reset_kernel<<<(BATCH * HDIM + 511) / 512, 512>>>(h0);
    decoder_kernel<<<GRID, NTHR, SMEM_BYTES>>>(emb, Wih0, Whh0, bih0, bhh0,
                                               Wih1, Whh1, bih1, bhh1,
                                               Wout, bout, dof, doi, mode);
}

// round 11
// speedup vs baseline: 2.2560x; 1.0852x over previous
#include <cuda_runtime.h>
#include <cstdint>
#include <cstddef>

// Problem constants
#define HDIM   512
#define BATCH  32
#define VOCAB  32000
#define MAXN   64
#define SOS_TOK 1

#define GRID   128                 // persistent CTAs (all resident)
#define NTHR   256

// logits tiling
#define LROWS  256
#define NCAND  (VOCAB / LROWS)     // 125
// gates tiling
#define GROWS  3072                // 2*3*HDIM gate rows (x-side 0..1535, h-side 1536..3071)
#define KSPLIT 8
#define KSL    (HDIM / KSPLIT)     // 64
#define GATE_CTAS (GROWS / NTHR * KSPLIT)   // 96

// -------- persistent scratch --------
__device__ float g_h0[2][BATCH * HDIM];
__device__ float g_h1[2][BATCH * HDIM];
__device__ float g_part[KSPLIT * BATCH * GROWS];
__device__ float g_cval[NCAND * BATCH];
__device__ int   g_cidx[NCAND * BATCH];
__device__ volatile unsigned g_bar_count;

// -------- packed fp32x2 FMA --------
__device__ __forceinline__ float2 ffma2(float2 a, float2 b, float2 c) {
    unsigned long long ua = *reinterpret_cast<unsigned long long*>(&a);
    unsigned long long ub = *reinterpret_cast<unsigned long long*>(&b);
    unsigned long long uc = *reinterpret_cast<unsigned long long*>(&c);
    unsigned long long ud;
    asm("fma.rn.f32x2 %0, %1, %2, %3;" : "=l"(ud) : "l"(ua), "l"(ub), "l"(uc));
    return *reinterpret_cast<float2*>(&ud);
}

// -------- minimal-op fp64 transcendentals (B300 FP64 pipe is slow) --------
// exp(x), |x| < ~600: range-reduce to 2^n * e^g, |g| <= ln2/2, Taylor deg-10.
__device__ __forceinline__ double exp_fast(double x) {
    double t = x * 1.4426950408889634;       // x * log2(e)
    int    fn = __double2int_rn(t);
    double f  = t - (double)fn;              // |f| <= 0.5
    double g  = f * 0.6931471805599453;      // |g| <= 0.3466
    double p  = 2.7557319223985893e-07;      // 1/10!
    p = fma(p, g, 2.755731922398589e-06);    // 1/9!
    p = fma(p, g, 2.4801587301587302e-05);   // 1/8!
    p = fma(p, g, 1.9841269841269841e-04);   // 1/7!
    p = fma(p, g, 1.3888888888888889e-03);   // 1/6!
    p = fma(p, g, 8.3333333333333332e-03);   // 1/5!
    p = fma(p, g, 4.1666666666666664e-02);   // 1/4!
    p = fma(p, g, 1.6666666666666666e-01);   // 1/3!
    p = fma(p, g, 0.5);
    p = fma(p, g, 1.0);
    p = fma(p, g, 1.0);
    double s = __longlong_as_double(((long long)(fn + 1023)) << 52);
    return p * s;
}

// 1/u for u > 0 (u ~ O(1)): fp32 MUFU seed + 2 fp64 Newton steps (~1e-16).
__device__ __forceinline__ double rcp_fast(double u) {
    float rf;
    asm("rcp.approx.f32 %0, %1;" : "=f"(rf) : "f"((float)u));
    double r = (double)rf;
    r = fma(r, fma(-u, r, 1.0), r);
    r = fma(r, fma(-u, r, 1.0), r);
    return r;
}

__device__ __forceinline__ double sigmoid_fast(double x) {
    return rcp_fast(1.0 + exp_fast(-x));
}

__device__ __forceinline__ double tanh_fast(double y) {
    double a  = fabs(y);
    double e  = exp_fast(-2.0 * a);
    double th = (1.0 - e) * rcp_fast(1.0 + e);
    return (y < 0.0) ? -th : th;
}

#define MODE_INT_TOK   0
#define MODE_FLOAT_ALL 1
#define MODE_FLOAT_H   2

// -------- grid barrier: monotonic counter, per-CTA epoch --------
__device__ __forceinline__ void gbar(unsigned& epoch) {
    __threadfence();
    __syncthreads();
    if (threadIdx.x == 0) {
        epoch += 1;
        unsigned target = epoch * (unsigned)GRID;
        atomicAdd((unsigned*)&g_bar_count, 1u);
        while (g_bar_count < target) { }
        __threadfence();
    }
    __syncthreads();
}

// ---------------------------------------------------------------
__global__ void reset_kernel(const float* __restrict__ h0in) {
    int i = blockIdx.x * blockDim.x + threadIdx.x;
    if (i == 0) g_bar_count = 0;
    if (i < BATCH * HDIM) {
        g_h0[0][i] = h0in[i];
        g_h1[0][i] = h0in[BATCH * HDIM + i];
    }
}

// -------- smem layout --------
#define WT_STRIDE 33
#define WT_FLOATS (LROWS * WT_STRIDE)            // 8448
#define HS_FLOATS (BATCH * HDIM)                 // 16384
#define SMEM_BYTES ((HS_FLOATS + 2 * WT_FLOATS) * 4)   // 133120

__device__ __forceinline__ void stage_w(const float* __restrict__ Wout, int v0,
                                        int c, float* wb, int tid)
{
    const int rr = tid >> 3;
    const int pp = tid & 7;
    #pragma unroll
    for (int pass = 0; pass < 8; pass++) {
        int row = pass * 32 + rr;
        float4 w = *(const float4*)(Wout + (size_t)(v0 + row) * HDIM + c * 32 + pp * 4);
        float* d = wb + row * WT_STRIDE + pp * 4;
        d[0] = w.x; d[1] = w.y; d[2] = w.z; d[3] = w.w;
    }
}

// ---------------------------------------------------------------
__global__ __launch_bounds__(NTHR, 1)
void decoder_kernel(const float* __restrict__ emb,
                    const float* __restrict__ Wih0, const float* __restrict__ Whh0,
                    const float* __restrict__ bih0, const float* __restrict__ bhh0,
                    const float* __restrict__ Wih1, const float* __restrict__ Whh1,
                    const float* __restrict__ bih1, const float* __restrict__ bhh1,
                    const float* __restrict__ Wout, const float* __restrict__ bout,
                    float* __restrict__ dout_f, int* __restrict__ dout_i, int mode)
{
    extern __shared__ float sm[];
    float* hsm = sm;                         // logits: h1 [32][512]
    float* wt0 = sm + HS_FLOATS;
    float* wt1 = wt0 + WT_FLOATS;
    float* xs  = sm;                         // gates: x slice [32][64]
    float* hs  = sm + BATCH * KSL;           // gates: h slice [32][64]

    __shared__ float rv[NTHR];
    __shared__ int   ri[NTHR];
    __shared__ int   stok[BATCH];
    __shared__ float wval[8][BATCH];
    __shared__ int   widx[8][BATCH];

    const int cta = blockIdx.x;
    const int tid = threadIdx.x;
    unsigned epoch = 0;

    for (int t = 0; t < MAXN; t++) {
        const int rp = t & 1, wp = 1 - rp;

        // ================= token resolve (per-CTA, redundant) =================
        if (t == 0) {
            if (tid < BATCH) stok[tid] = SOS_TOK;
            __syncthreads();
        } else {
            const int b = tid >> 3, c8 = tid & 7;
            float best = -3.4e38f; int bi = 0x7fffffff;
            for (int cnd = c8; cnd < NCAND; cnd += 8) {
                float v  = __ldcg(&g_cval[cnd * BATCH + b]);
                int   ix = __ldcg(&g_cidx[cnd * BATCH + b]);
                if (v > best || (v == best && ix < bi)) { best = v; bi = ix; }
            }
            rv[tid] = best; ri[tid] = bi;
            __syncthreads();
            if (c8 == 0) {
                #pragma unroll
                for (int w = 1; w < 8; w++) {
                    float ov = rv[tid + w]; int oi = ri[tid + w];
                    if (ov > best || (ov == best && oi < bi)) { best = ov; bi = oi; }
                }
                stok[b] = bi;
                if (cta == 0) {
                    if (mode == MODE_INT_TOK)        dout_i[b * MAXN + (t - 1)] = bi;
                    else if (mode == MODE_FLOAT_ALL) dout_f[b * MAXN + (t - 1)] = (float)bi;
                }
            }
            __syncthreads();
        }

        // ================= two GRU layers =================
        #pragma unroll 1
        for (int layer = 0; layer < 2; layer++) {
            const float* Wih = layer ? Wih1 : Wih0;
            const float* Whh = layer ? Whh1 : Whh0;

            if (cta < GATE_CTAS) {
                const int ks  = cta / 12;
                const int row = (cta % 12) * NTHR + tid;     // 0..3071
                const bool xside = (row < 1536);
                const int wrow = xside ? row : (row - 1536);

                for (int i = tid; i < BATCH * (KSL / 4); i += NTHR) {
                    int b = i / (KSL / 4), f = i % (KSL / 4);
                    float4 xv;
                    if (layer == 0)
                        xv = *(const float4*)(emb + (size_t)stok[b] * HDIM + ks * KSL + f * 4);
                    else
                        xv = __ldcg((const float4*)(&g_h0[wp][0] + b * HDIM + ks * KSL + f * 4));
                    ((float4*)xs)[b * (KSL / 4) + f] = xv;
                    const float* hsrc = layer ? &g_h1[rp][0] : &g_h0[rp][0];
                    ((float4*)hs)[b * (KSL / 4) + f] =
                        __ldcg((const float4*)(hsrc + b * HDIM + ks * KSL + f * 4));
                }
                __syncthreads();

                const float4* W4   = (const float4*)((xside ? Wih : Whh) +
                                      (size_t)wrow * HDIM + ks * KSL);
                const float4* src4 = (const float4*)(xside ? xs : hs);

                float2 acc[BATCH];
                #pragma unroll
                for (int b = 0; b < BATCH; b++) acc[b] = make_float2(0.f, 0.f);

                #pragma unroll
                for (int c = 0; c < KSL / 16; c++) {
                    float4 w0 = W4[c * 4 + 0], w1 = W4[c * 4 + 1];
                    float4 w2 = W4[c * 4 + 2], w3 = W4[c * 4 + 3];
                    float2 wl0 = make_float2(w0.x, w0.y), wh0 = make_float2(w0.z, w0.w);
                    float2 wl1 = make_float2(w1.x, w1.y), wh1 = make_float2(w1.z, w1.w);
                    float2 wl2 = make_float2(w2.x, w2.y), wh2 = make_float2(w2.z, w2.w);
                    float2 wl3 = make_float2(w3.x, w3.y), wh3 = make_float2(w3.z, w3.w);
                    #pragma unroll
                    for (int b = 0; b < BATCH; b++) {
                        const float4* hb = src4 + b * (KSL / 4) + c * 4;
                        float4 a0 = hb[0], a1 = hb[1], a2 = hb[2], a3 = hb[3];
                        float2 s = acc[b];
                        s = ffma2(wl0, make_float2(a0.x, a0.y), s);
                        s = ffma2(wh0, make_float2(a0.z, a0.w), s);
                        s = ffma2(wl1, make_float2(a1.x, a1.y), s);
                        s = ffma2(wh1, make_float2(a1.z, a1.w), s);
                        s = ffma2(wl2, make_float2(a2.x, a2.y), s);
                        s = ffma2(wh2, make_float2(a2.z, a2.w), s);
                        s = ffma2(wl3, make_float2(a3.x, a3.y), s);
                        s = ffma2(wh3, make_float2(a3.z, a3.w), s);
                        acc[b] = s;
                    }
                }

                #pragma unroll
                for (int b = 0; b < BATCH; b++)
                    __stcg(&g_part[(size_t)(ks * BATCH + b) * GROWS + row],
                           acc[b].x + acc[b].y);
            }
            gbar(epoch);

            // -------- activation: 128 elems per CTA, all 128 CTAs busy --------
            if (tid < 128) {
                const int gt = cta * 128 + tid;          // 0..16383, exact cover
                const int b = gt >> 9, j = gt & 511;
                const float* bih = layer ? bih1 : bih0;
                const float* bhh = layer ? bhh1 : bhh0;

                float gir = 0.f, giz = 0.f, gin = 0.f, ghr = 0.f, ghz = 0.f, ghn = 0.f;
                #pragma unroll
                for (int kp = 0; kp < KSPLIT; kp++) {
                    const float* P = g_part + (size_t)(kp * BATCH + b) * GROWS;
                    gir += __ldcg(&P[j]);          giz += __ldcg(&P[j + 512]);
                    gin += __ldcg(&P[j + 1024]);   ghr += __ldcg(&P[1536 + j]);
                    ghz += __ldcg(&P[2048 + j]);   ghn += __ldcg(&P[2560 + j]);
                }
                gir += bih[j]; giz += bih[512 + j]; gin += bih[1024 + j];
                ghr += bhh[j]; ghz += bhh[512 + j]; ghn += bhh[1024 + j];

                float* hbuf = layer ? &g_h1[0][0] : &g_h0[0][0];
                float hprev = __ldcg(&hbuf[rp * BATCH * HDIM + b * HDIM + j]);

                double r = sigmoid_fast((double)(gir + ghr));
                double z = sigmoid_fast((double)(giz + ghz));
                double n = tanh_fast((double)gin + r * (double)ghn);
                __stcg(&hbuf[wp * BATCH * HDIM + b * HDIM + j],
                       (float)((1.0 - z) * n + z * (double)hprev));
            }
            gbar(epoch);
        }

        // ================= logits + per-CTA candidates =================
        if (cta < NCAND) {
            const int v0 = cta * LROWS;

            {
                const float4* src = (const float4*)(&g_h1[wp][0]);
                for (int i = tid; i < HS_FLOATS / 4; i += NTHR)
                    ((float4*)hsm)[i] = __ldcg(&src[i]);
            }
            stage_w(Wout, v0, 0, wt0, tid);
            __syncthreads();

            float2 acc[BATCH];
            #pragma unroll
            for (int b = 0; b < BATCH; b++) acc[b] = make_float2(0.f, 0.f);

            for (int c = 0; c < HDIM / 32; c++) {
                float* wcur = (c & 1) ? wt1 : wt0;
                if (c + 1 < HDIM / 32) {
                    float* wnxt = ((c + 1) & 1) ? wt1 : wt0;
                    stage_w(Wout, v0, c + 1, wnxt, tid);
                }
                float wreg[32];
                #pragma unroll
                for (int k = 0; k < 32; k++) wreg[k] = wcur[tid * WT_STRIDE + k];

                #pragma unroll
                for (int b = 0; b < BATCH; b++) {
                    const float4* hb = (const float4*)(hsm + b * HDIM + c * 32);
                    float2 s = acc[b];
                    #pragma unroll
                    for (int q = 0; q < 8; q++) {
                        float4 a = hb[q];
                        s = ffma2(make_float2(wreg[q * 4 + 0], wreg[q * 4 + 1]),
                                  make_float2(a.x, a.y), s);
                        s = ffma2(make_float2(wreg[q * 4 + 2], wreg[q * 4 + 3]),
                                  make_float2(a.z, a.w), s);
                    }
                    acc[b] = s;
                }
                __syncthreads();
            }

            const float bv = bout[v0 + tid];
            const int warp = tid >> 5, lane = tid & 31;

            #pragma unroll
            for (int b = 0; b < BATCH; b++) {
                float val = acc[b].x + acc[b].y + bv;
                int   idx = v0 + tid;
                #pragma unroll
                for (int m = 16; m > 0; m >>= 1) {
                    float ov = __shfl_xor_sync(0xffffffffu, val, m);
                    int   oi = __shfl_xor_sync(0xffffffffu, idx, m);
                    if (ov > val || (ov == val && oi < idx)) { val = ov; idx = oi; }
                }
                if (lane == 0) { wval[warp][b] = val; widx[warp][b] = idx; }
            }
            __syncthreads();

            if (tid < BATCH) {
                int b = tid;
                float best = wval[0][b]; int bi = widx[0][b];
                #pragma unroll
                for (int w = 1; w < 8; w++) {
                    float ov = wval[w][b]; int oi = widx[w][b];
                    if (ov > best || (ov == best && oi < bi)) { best = ov; bi = oi; }
                }
                __stcg(&g_cval[cta * BATCH + b], best);
                __stcg(&g_cidx[cta * BATCH + b], bi);
            }
        }
        gbar(epoch);
    }

    // ================= epilogue: token 63 + h_t =================
    if (cta == 0) {
        const int b = tid >> 3, c8 = tid & 7;
        float best = -3.4e38f; int bi = 0x7fffffff;
        for (int cnd = c8; cnd < NCAND; cnd += 8) {
            float v  = __ldcg(&g_cval[cnd * BATCH + b]);
            int   ix = __ldcg(&g_cidx[cnd * BATCH + b]);
            if (v > best || (v == best && ix < bi)) { best = v; bi = ix; }
        }
        rv[tid] = best; ri[tid] = bi;
        __syncthreads();
        if (c8 == 0) {
            #pragma unroll
            for (int w = 1; w < 8; w++) {
                float ov = rv[tid + w]; int oi = ri[tid + w];
                if (ov > best || (ov == best && oi < bi)) { best = ov; bi = oi; }
            }
            if (mode == MODE_INT_TOK)        dout_i[b * MAXN + (MAXN - 1)] = bi;
            else if (mode == MODE_FLOAT_ALL) dout_f[b * MAXN + (MAXN - 1)] = (float)bi;
        }
    }
    if (mode != MODE_INT_TOK && cta >= 1 && cta <= BATCH) {
        const int b = cta - 1;
        const int off = (mode == MODE_FLOAT_ALL) ? (BATCH * MAXN) : 0;
        for (int k = tid; k < HDIM; k += NTHR) {
            dout_f[off + b * HDIM + k]                = __ldcg(&g_h0[0][b * HDIM + k]);
            dout_f[off + BATCH * HDIM + b * HDIM + k] = __ldcg(&g_h1[0][b * HDIM + k]);
        }
    }
}

// ---------------------------------------------------------------
extern "C" void kernel_launch(void* const* d_in, const int* in_sizes, int n_in,
                              void* d_out, int out_size)
{
    const float* h0   = (const float*)d_in[0];
    const float* emb  = (const float*)d_in[1];
    const float* Wih0 = (const float*)d_in[2];
    const float* Whh0 = (const float*)d_in[3];
    const float* bih0 = (const float*)d_in[4];
    const float* bhh0 = (const float*)d_in[5];
    const float* Wih1 = (const float*)d_in[6];
    const float* Whh1 = (const float*)d_in[7];
    const float* bih1 = (const float*)d_in[8];
    const float* bhh1 = (const float*)d_in[9];
    const float* Wout = (const float*)d_in[10];
    const float* bout = (const float*)d_in[11];

    int mode;
    if (out_size == BATCH * MAXN)          mode = MODE_INT_TOK;
    else if (out_size == 2 * BATCH * HDIM) mode = MODE_FLOAT_H;
    else                                   mode = MODE_FLOAT_ALL;

    float* dof = (float*)d_out;
    int*   doi = (int*)d_out;

    cudaFuncSetAttribute(decoder_kernel, cudaFuncAttributeMaxDynamicSharedMemorySize,
                         SMEM_BYTES);

    reset_kernel<<<(BATCH * HDIM + 511) / 512, 512>>>(h0);
    decoder_kernel<<<GRID, NTHR, SMEM_BYTES>>>(emb, Wih0, Whh0, bih0, bhh0,
                                               Wih1, Whh1, bih1, bhh1,
                                               Wout, bout, dof, doi, mode);
}

// round 13
// speedup vs baseline: 2.4235x; 1.0742x over previous
#include <cuda_runtime.h>
#include <cuda_bf16.h>
#include <cstdint>
#include <cstddef>

// Problem constants
#define HDIM   512
#define BATCH  32
#define VOCAB  32000
#define MAXN   64
#define SOS_TOK 1

#define GRID   128
#define NTHR   256

// logits tiling
#define LROWS  256
#define NCAND  (VOCAB / LROWS)     // 125
// gates tiling
#define GROWS  3072
#define KSPLIT 8
#define KSL    (HDIM / KSPLIT)     // 64
#define GATE_CTAS (GROWS / NTHR * KSPLIT)   // 96

// -------- persistent scratch --------
__device__ float g_h0[2][BATCH * HDIM];
__device__ float g_h1[2][BATCH * HDIM];
__device__ float g_part[KSPLIT * BATCH * GROWS];
__device__ float g_cval[NCAND * BATCH];
__device__ int   g_cidx[NCAND * BATCH];
__device__ volatile unsigned g_bar_count;

// Pre-split W_out as bf16, row-major [32000][512], 3 splits (b32 = bf16x2 pairs)
#define WB_U32 (VOCAB * 256)                     // b32 words per split
__device__ __align__(16) uint32_t g_Wb[3][WB_U32];   // 3 x 32.768 MB

// -------- packed fp32x2 FMA --------
__device__ __forceinline__ float2 ffma2(float2 a, float2 b, float2 c) {
    unsigned long long ua = *reinterpret_cast<unsigned long long*>(&a);
    unsigned long long ub = *reinterpret_cast<unsigned long long*>(&b);
    unsigned long long uc = *reinterpret_cast<unsigned long long*>(&c);
    unsigned long long ud;
    asm("fma.rn.f32x2 %0, %1, %2, %3;" : "=l"(ud) : "l"(ua), "l"(ub), "l"(uc));
    return *reinterpret_cast<float2*>(&ud);
}

// -------- minimal-op fp64 transcendentals --------
__device__ __forceinline__ double exp_fast(double x) {
    double t = x * 1.4426950408889634;
    int    fn = __double2int_rn(t);
    double g  = (t - (double)fn) * 0.6931471805599453;
    double p  = 2.7557319223985893e-07;
    p = fma(p, g, 2.755731922398589e-06);
    p = fma(p, g, 2.4801587301587302e-05);
    p = fma(p, g, 1.9841269841269841e-04);
    p = fma(p, g, 1.3888888888888889e-03);
    p = fma(p, g, 8.3333333333333332e-03);
    p = fma(p, g, 4.1666666666666664e-02);
    p = fma(p, g, 1.6666666666666666e-01);
    p = fma(p, g, 0.5);
    p = fma(p, g, 1.0);
    p = fma(p, g, 1.0);
    return p * __longlong_as_double(((long long)(fn + 1023)) << 52);
}
__device__ __forceinline__ double rcp_fast(double u) {
    float rf;
    asm("rcp.approx.f32 %0, %1;" : "=f"(rf) : "f"((float)u));
    double r = (double)rf;
    r = fma(r, fma(-u, r, 1.0), r);
    r = fma(r, fma(-u, r, 1.0), r);
    return r;
}
__device__ __forceinline__ double sigmoid_fast(double x) { return rcp_fast(1.0 + exp_fast(-x)); }
__device__ __forceinline__ double tanh_fast(double y) {
    double a  = fabs(y);
    double e  = exp_fast(-2.0 * a);
    double th = (1.0 - e) * rcp_fast(1.0 + e);
    return (y < 0.0) ? -th : th;
}

#define MODE_INT_TOK   0
#define MODE_FLOAT_ALL 1
#define MODE_FLOAT_H   2

// -------- grid barrier --------
__device__ __forceinline__ void gbar(unsigned& epoch) {
    __threadfence();
    __syncthreads();
    if (threadIdx.x == 0) {
        epoch += 1;
        unsigned target = epoch * (unsigned)GRID;
        atomicAdd((unsigned*)&g_bar_count, 1u);
        while (g_bar_count < target) { }
        __threadfence();
    }
    __syncthreads();
}

// -------- warp-level bf16 MMA (baseline sm_80+ feature, no 'a' target needed) --------
__device__ __forceinline__ void mma_bf16(float* c, uint32_t a0, uint32_t a1,
                                         uint32_t a2, uint32_t a3,
                                         uint32_t b0, uint32_t b1) {
    asm volatile(
        "mma.sync.aligned.m16n8k16.row.col.f32.bf16.bf16.f32 "
        "{%0,%1,%2,%3}, {%4,%5,%6,%7}, {%8,%9}, {%0,%1,%2,%3};"
        : "+f"(c[0]), "+f"(c[1]), "+f"(c[2]), "+f"(c[3])
        : "r"(a0), "r"(a1), "r"(a2), "r"(a3), "r"(b0), "r"(b1));
}

// split one 8-float group into 3 bf16x8 (packed uint4 each)
__device__ __forceinline__ void split8(const float* w, uint4& o1, uint4& o2, uint4& o3) {
    unsigned r1[4], r2[4], r3[4];
    #pragma unroll
    for (int p = 0; p < 4; p++) {
        float a = w[2*p], b = w[2*p+1];
        __nv_bfloat16 a1 = __float2bfloat16(a);
        __nv_bfloat16 b1 = __float2bfloat16(b);
        float ar = a - __bfloat162float(a1);
        float br = b - __bfloat162float(b1);
        __nv_bfloat16 a2 = __float2bfloat16(ar);
        __nv_bfloat16 b2 = __float2bfloat16(br);
        __nv_bfloat16 a3 = __float2bfloat16(ar - __bfloat162float(a2));
        __nv_bfloat16 b3 = __float2bfloat16(br - __bfloat162float(b2));
        __nv_bfloat162 t1 = __halves2bfloat162(a1, b1);
        __nv_bfloat162 t2 = __halves2bfloat162(a2, b2);
        __nv_bfloat162 t3 = __halves2bfloat162(a3, b3);
        r1[p] = *(unsigned*)&t1; r2[p] = *(unsigned*)&t2; r3[p] = *(unsigned*)&t3;
    }
    o1 = make_uint4(r1[0], r1[1], r1[2], r1[3]);
    o2 = make_uint4(r2[0], r2[1], r2[2], r2[3]);
    o3 = make_uint4(r3[0], r3[1], r3[2], r3[3]);
}

// ---------------------------------------------------------------
__global__ void reset_kernel(const float* __restrict__ h0in) {
    int i = blockIdx.x * blockDim.x + threadIdx.x;
    if (i == 0) g_bar_count = 0;
    if (i < BATCH * HDIM) {
        g_h0[0][i] = h0in[i];
        g_h1[0][i] = h0in[BATCH * HDIM + i];
    }
}

// -------- smem layout (floats) --------
// Hsm: 3 splits x 32 rows x 260 b32 (= 512 bf16 + pad)  -> 24960 words
// Dsm: 256 x 33 f32                                     ->  8448 words
#define HS_STRIDE 260
#define HS_SPLIT  (BATCH * HS_STRIDE)        // 8320 b32 per split
#define HS_WORDS  (3 * HS_SPLIT)             // 24960
#define DS_OFF    HS_WORDS
#define SMEM_WORDS (HS_WORDS + LROWS * 33)   // 33408
#define SMEM_BYTES (SMEM_WORDS * 4)          // 133632

// ---------------------------------------------------------------
__global__ __launch_bounds__(NTHR, 1)
void decoder_kernel(const float* __restrict__ emb,
                    const float* __restrict__ Wih0, const float* __restrict__ Whh0,
                    const float* __restrict__ bih0, const float* __restrict__ bhh0,
                    const float* __restrict__ Wih1, const float* __restrict__ Whh1,
                    const float* __restrict__ bih1, const float* __restrict__ bhh1,
                    const float* __restrict__ Wout, const float* __restrict__ bout,
                    float* __restrict__ dout_f, int* __restrict__ dout_i, int mode)
{
    extern __shared__ float sm[];
    uint32_t* Hsm = (uint32_t*)sm;           // logits B splits (bf16x2 words)
    float*    Dsm = sm + DS_OFF;             // logits output tile
    float*    xs  = sm;                      // gates aliases
    float*    hs  = sm + BATCH * KSL;

    __shared__ float rv[NTHR];
    __shared__ int   ri[NTHR];
    __shared__ int   stok[BATCH];

    const int cta = blockIdx.x;
    const int tid = threadIdx.x;
    const int wid = tid >> 5;
    const int lane = tid & 31;
    unsigned epoch = 0;

    // ================= prologue: W bf16x3 split (once per launch) =================
    {
        const int NGRP = VOCAB * (HDIM / 8);          // 2,048,000
        for (int gi = cta * NTHR + tid; gi < NGRP; gi += GRID * NTHR) {
            int r = gi >> 6, kg = gi & 63;
            const float* src = Wout + (size_t)r * HDIM + kg * 8;
            float4 f0 = *(const float4*)src;
            float4 f1 = *(const float4*)(src + 4);
            float w[8] = {f0.x, f0.y, f0.z, f0.w, f1.x, f1.y, f1.z, f1.w};
            uint4 o1, o2, o3; split8(w, o1, o2, o3);
            size_t u4 = (size_t)r * 64 + kg;
            ((uint4*)g_Wb[0])[u4] = o1;
            ((uint4*)g_Wb[1])[u4] = o2;
            ((uint4*)g_Wb[2])[u4] = o3;
        }
    }
    gbar(epoch);

    for (int t = 0; t < MAXN; t++) {
        const int rp = t & 1, wp = 1 - rp;

        // ================= token resolve =================
        if (t == 0) {
            if (tid < BATCH) stok[tid] = SOS_TOK;
            __syncthreads();
        } else {
            const int b = tid >> 3, c8 = tid & 7;
            float best = -3.4e38f; int bi = 0x7fffffff;
            for (int cnd = c8; cnd < NCAND; cnd += 8) {
                float v  = __ldcg(&g_cval[cnd * BATCH + b]);
                int   ix = __ldcg(&g_cidx[cnd * BATCH + b]);
                if (v > best || (v == best && ix < bi)) { best = v; bi = ix; }
            }
            rv[tid] = best; ri[tid] = bi;
            __syncthreads();
            if (c8 == 0) {
                #pragma unroll
                for (int w = 1; w < 8; w++) {
                    float ov = rv[tid + w]; int oi = ri[tid + w];
                    if (ov > best || (ov == best && oi < bi)) { best = ov; bi = oi; }
                }
                stok[b] = bi;
                if (cta == 0) {
                    if (mode == MODE_INT_TOK)        dout_i[b * MAXN + (t - 1)] = bi;
                    else if (mode == MODE_FLOAT_ALL) dout_f[b * MAXN + (t - 1)] = (float)bi;
                }
            }
            __syncthreads();
        }

        // ================= two GRU layers (scalar, known-good) =================
        #pragma unroll 1
        for (int layer = 0; layer < 2; layer++) {
            const float* Wih = layer ? Wih1 : Wih0;
            const float* Whh = layer ? Whh1 : Whh0;

            if (cta < GATE_CTAS) {
                const int ks  = cta / 12;
                const int row = (cta % 12) * NTHR + tid;
                const bool xside = (row < 1536);
                const int wrow = xside ? row : (row - 1536);

                for (int i = tid; i < BATCH * (KSL / 4); i += NTHR) {
                    int b = i / (KSL / 4), f = i % (KSL / 4);
                    float4 xv;
                    if (layer == 0)
                        xv = *(const float4*)(emb + (size_t)stok[b] * HDIM + ks * KSL + f * 4);
                    else
                        xv = __ldcg((const float4*)(&g_h0[wp][0] + b * HDIM + ks * KSL + f * 4));
                    ((float4*)xs)[b * (KSL / 4) + f] = xv;
                    const float* hsrc = layer ? &g_h1[rp][0] : &g_h0[rp][0];
                    ((float4*)hs)[b * (KSL / 4) + f] =
                        __ldcg((const float4*)(hsrc + b * HDIM + ks * KSL + f * 4));
                }
                __syncthreads();

                const float4* W4   = (const float4*)((xside ? Wih : Whh) +
                                      (size_t)wrow * HDIM + ks * KSL);
                const float4* src4 = (const float4*)(xside ? xs : hs);

                float2 acc[BATCH];
                #pragma unroll
                for (int b = 0; b < BATCH; b++) acc[b] = make_float2(0.f, 0.f);

                #pragma unroll
                for (int c = 0; c < KSL / 16; c++) {
                    float4 w0 = W4[c * 4 + 0], w1 = W4[c * 4 + 1];
                    float4 w2 = W4[c * 4 + 2], w3 = W4[c * 4 + 3];
                    float2 wl0 = make_float2(w0.x, w0.y), wh0 = make_float2(w0.z, w0.w);
                    float2 wl1 = make_float2(w1.x, w1.y), wh1 = make_float2(w1.z, w1.w);
                    float2 wl2 = make_float2(w2.x, w2.y), wh2 = make_float2(w2.z, w2.w);
                    float2 wl3 = make_float2(w3.x, w3.y), wh3 = make_float2(w3.z, w3.w);
                    #pragma unroll
                    for (int b = 0; b < BATCH; b++) {
                        const float4* hb = src4 + b * (KSL / 4) + c * 4;
                        float4 a0 = hb[0], a1 = hb[1], a2 = hb[2], a3 = hb[3];
                        float2 s = acc[b];
                        s = ffma2(wl0, make_float2(a0.x, a0.y), s);
                        s = ffma2(wh0, make_float2(a0.z, a0.w), s);
                        s = ffma2(wl1, make_float2(a1.x, a1.y), s);
                        s = ffma2(wh1, make_float2(a1.z, a1.w), s);
                        s = ffma2(wl2, make_float2(a2.x, a2.y), s);
                        s = ffma2(wh2, make_float2(a2.z, a2.w), s);
                        s = ffma2(wl3, make_float2(a3.x, a3.y), s);
                        s = ffma2(wh3, make_float2(a3.z, a3.w), s);
                        acc[b] = s;
                    }
                }

                #pragma unroll
                for (int b = 0; b < BATCH; b++)
                    __stcg(&g_part[(size_t)(ks * BATCH + b) * GROWS + row],
                           acc[b].x + acc[b].y);
            }
            gbar(epoch);

            if (tid < 128) {
                const int gt = cta * 128 + tid;
                const int b = gt >> 9, j = gt & 511;
                const float* bih = layer ? bih1 : bih0;
                const float* bhh = layer ? bhh1 : bhh0;

                float gir = 0.f, giz = 0.f, gin = 0.f, ghr = 0.f, ghz = 0.f, ghn = 0.f;
                #pragma unroll
                for (int kp = 0; kp < KSPLIT; kp++) {
                    const float* P = g_part + (size_t)(kp * BATCH + b) * GROWS;
                    gir += __ldcg(&P[j]);          giz += __ldcg(&P[j + 512]);
                    gin += __ldcg(&P[j + 1024]);   ghr += __ldcg(&P[1536 + j]);
                    ghz += __ldcg(&P[2048 + j]);   ghn += __ldcg(&P[2560 + j]);
                }
                gir += bih[j]; giz += bih[512 + j]; gin += bih[1024 + j];
                ghr += bhh[j]; ghz += bhh[512 + j]; ghn += bhh[1024 + j];

                float* hbuf = layer ? &g_h1[0][0] : &g_h0[0][0];
                float hprev = __ldcg(&hbuf[rp * BATCH * HDIM + b * HDIM + j]);

                double r = sigmoid_fast((double)(gir + ghr));
                double z = sigmoid_fast((double)(giz + ghz));
                double n = tanh_fast((double)gin + r * (double)ghn);
                __stcg(&hbuf[wp * BATCH * HDIM + b * HDIM + j],
                       (float)((1.0 - z) * n + z * (double)hprev));
            }
            gbar(epoch);
        }

        // ================= logits: bf16x3 via mma.sync =================
        if (cta < NCAND) {
            const int v0 = cta * LROWS;

            // ---- stage h splits into padded smem (B operand) ----
            {
                const float* hsrc = &g_h1[wp][0];
                for (int i = tid; i < 2048; i += NTHR) {     // 2048 groups of 8
                    int b = i >> 6, kg = i & 63;
                    float4 f0 = __ldcg((const float4*)(hsrc + b * HDIM + kg * 8));
                    float4 f1 = __ldcg((const float4*)(hsrc + b * HDIM + kg * 8 + 4));
                    float w[8] = {f0.x, f0.y, f0.z, f0.w, f1.x, f1.y, f1.z, f1.w};
                    uint4 o1, o2, o3; split8(w, o1, o2, o3);
                    ((uint4*)Hsm)[(0 * HS_SPLIT + b * HS_STRIDE) / 4 + kg] = o1;
                    ((uint4*)Hsm)[(1 * HS_SPLIT + b * HS_STRIDE) / 4 + kg] = o2;
                    ((uint4*)Hsm)[(2 * HS_SPLIT + b * HS_STRIDE) / 4 + kg] = o3;
                }
            }
            __syncthreads();

            // ---- mma mainloop: warp = 32 vocab rows (2 M-tiles), N=32, K=512 ----
            const int g  = lane >> 2;      // 0..7
            const int tg = lane & 3;       // 0..3

            // A gmem b32 bases per (mtile, split)
            const uint32_t* Ap[2][3];
            #pragma unroll
            for (int mt = 0; mt < 2; mt++) {
                int row0 = v0 + wid * 32 + mt * 16 + g;
                #pragma unroll
                for (int s = 0; s < 3; s++)
                    Ap[mt][s] = g_Wb[s] + (size_t)row0 * 256 + tg;
            }
            // B smem b32 bases per (ntile, split)
            uint32_t Bb[4][3];
            #pragma unroll
            for (int nt = 0; nt < 4; nt++)
                #pragma unroll
                for (int s = 0; s < 3; s++)
                    Bb[nt][s] = s * HS_SPLIT + (nt * 8 + g) * HS_STRIDE + tg;

            float acc[2][4][4];
            #pragma unroll
            for (int mt = 0; mt < 2; mt++)
                #pragma unroll
                for (int nt = 0; nt < 4; nt++)
                    #pragma unroll
                    for (int q = 0; q < 4; q++) acc[mt][nt][q] = 0.f;

            uint32_t A0[2][3][4], A1[2][3][4];
            // preload kh = 0
            #pragma unroll
            for (int mt = 0; mt < 2; mt++)
                #pragma unroll
                for (int s = 0; s < 3; s++) {
                    A0[mt][s][0] = Ap[mt][s][0];
                    A0[mt][s][1] = Ap[mt][s][2048];
                    A0[mt][s][2] = Ap[mt][s][4];
                    A0[mt][s][3] = Ap[mt][s][2052];
                }

            #pragma unroll 1
            for (int ks = 0; ks < 32; ks += 2) {
                const int kh = ks * 8;
                // ---- half A: prefetch kh+8 ----
                #pragma unroll
                for (int mt = 0; mt < 2; mt++)
                    #pragma unroll
                    for (int s = 0; s < 3; s++) {
                        const uint32_t* p = Ap[mt][s] + kh + 8;
                        A1[mt][s][0] = p[0];
                        A1[mt][s][1] = p[2048];
                        A1[mt][s][2] = p[4];
                        A1[mt][s][3] = p[2052];
                    }
                {
                    uint32_t Bf[4][3][2];
                    #pragma unroll
                    for (int nt = 0; nt < 4; nt++)
                        #pragma unroll
                        for (int s = 0; s < 3; s++) {
                            Bf[nt][s][0] = Hsm[Bb[nt][s] + kh];
                            Bf[nt][s][1] = Hsm[Bb[nt][s] + kh + 4];
                        }
                    #pragma unroll
                    for (int mt = 0; mt < 2; mt++)
                        #pragma unroll
                        for (int nt = 0; nt < 4; nt++) {
                            float* c = acc[mt][nt];
                            mma_bf16(c, A0[mt][0][0], A0[mt][0][1], A0[mt][0][2], A0[mt][0][3],
                                     Bf[nt][0][0], Bf[nt][0][1]);
                            mma_bf16(c, A0[mt][0][0], A0[mt][0][1], A0[mt][0][2], A0[mt][0][3],
                                     Bf[nt][1][0], Bf[nt][1][1]);
                            mma_bf16(c, A0[mt][1][0], A0[mt][1][1], A0[mt][1][2], A0[mt][1][3],
                                     Bf[nt][0][0], Bf[nt][0][1]);
                            mma_bf16(c, A0[mt][1][0], A0[mt][1][1], A0[mt][1][2], A0[mt][1][3],
                                     Bf[nt][1][0], Bf[nt][1][1]);
                            mma_bf16(c, A0[mt][0][0], A0[mt][0][1], A0[mt][0][2], A0[mt][0][3],
                                     Bf[nt][2][0], Bf[nt][2][1]);
                            mma_bf16(c, A0[mt][2][0], A0[mt][2][1], A0[mt][2][2], A0[mt][2][3],
                                     Bf[nt][0][0], Bf[nt][0][1]);
                        }
                }
                // ---- half B: prefetch kh+16 (guarded), mma with A1 ----
                const int khp = (ks + 2 < 32) ? (kh + 16) : 0;
                #pragma unroll
                for (int mt = 0; mt < 2; mt++)
                    #pragma unroll
                    for (int s = 0; s < 3; s++) {
                        const uint32_t* p = Ap[mt][s] + khp;
                        A0[mt][s][0] = p[0];
                        A0[mt][s][1] = p[2048];
                        A0[mt][s][2] = p[4];
                        A0[mt][s][3] = p[2052];
                    }
                {
                    uint32_t Bf[4][3][2];
                    #pragma unroll
                    for (int nt = 0; nt < 4; nt++)
                        #pragma unroll
                        for (int s = 0; s < 3; s++) {
                            Bf[nt][s][0] = Hsm[Bb[nt][s] + kh + 8];
                            Bf[nt][s][1] = Hsm[Bb[nt][s] + kh + 12];
                        }
                    #pragma unroll
                    for (int mt = 0; mt < 2; mt++)
                        #pragma unroll
                        for (int nt = 0; nt < 4; nt++) {
                            float* c = acc[mt][nt];
                            mma_bf16(c, A1[mt][0][0], A1[mt][0][1], A1[mt][0][2], A1[mt][0][3],
                                     Bf[nt][0][0], Bf[nt][0][1]);
                            mma_bf16(c, A1[mt][0][0], A1[mt][0][1], A1[mt][0][2], A1[mt][0][3],
                                     Bf[nt][1][0], Bf[nt][1][1]);
                            mma_bf16(c, A1[mt][1][0], A1[mt][1][1], A1[mt][1][2], A1[mt][1][3],
                                     Bf[nt][0][0], Bf[nt][0][1]);
                            mma_bf16(c, A1[mt][1][0], A1[mt][1][1], A1[mt][1][2], A1[mt][1][3],
                                     Bf[nt][1][0], Bf[nt][1][1]);
                            mma_bf16(c, A1[mt][0][0], A1[mt][0][1], A1[mt][0][2], A1[mt][0][3],
                                     Bf[nt][2][0], Bf[nt][2][1]);
                            mma_bf16(c, A1[mt][2][0], A1[mt][2][1], A1[mt][2][2], A1[mt][2][3],
                                     Bf[nt][0][0], Bf[nt][0][1]);
                        }
                }
            }

            // ---- dump D tile to smem ----
            #pragma unroll
            for (int mt = 0; mt < 2; mt++)
                #pragma unroll
                for (int nt = 0; nt < 4; nt++) {
                    int row = wid * 32 + mt * 16 + g;
                    int col = nt * 8 + 2 * tg;
                    Dsm[row * 33 + col]           = acc[mt][nt][0];
                    Dsm[row * 33 + col + 1]       = acc[mt][nt][1];
                    Dsm[(row + 8) * 33 + col]     = acc[mt][nt][2];
                    Dsm[(row + 8) * 33 + col + 1] = acc[mt][nt][3];
                }
            __syncthreads();

            // ---- argmax: thread = vocab row ----
            __shared__ float wval[8][BATCH];
            __shared__ int   widx[8][BATCH];

            const float bv = bout[v0 + tid];
            #pragma unroll
            for (int b = 0; b < BATCH; b++) {
                float val = Dsm[tid * 33 + b] + bv;
                int   idx = v0 + tid;
                #pragma unroll
                for (int m = 16; m > 0; m >>= 1) {
                    float ov = __shfl_xor_sync(0xffffffffu, val, m);
                    int   oi = __shfl_xor_sync(0xffffffffu, idx, m);
                    if (ov > val || (ov == val && oi < idx)) { val = ov; idx = oi; }
                }
                if (lane == 0) { wval[wid][b] = val; widx[wid][b] = idx; }
            }
            __syncthreads();

            if (tid < BATCH) {
                int b = tid;
                float best = wval[0][b]; int bi = widx[0][b];
                #pragma unroll
                for (int ww = 1; ww < 8; ww++) {
                    float ov = wval[ww][b]; int oi = widx[ww][b];
                    if (ov > best || (ov == best && oi < bi)) { best = ov; bi = oi; }
                }
                __stcg(&g_cval[cta * BATCH + b], best);
                __stcg(&g_cidx[cta * BATCH + b], bi);
            }
        }
        gbar(epoch);
    }

    // ================= epilogue: token 63 + h_t =================
    if (cta == 0) {
        const int b = tid >> 3, c8 = tid & 7;
        float best = -3.4e38f; int bi = 0x7fffffff;
        for (int cnd = c8; cnd < NCAND; cnd += 8) {
            float v  = __ldcg(&g_cval[cnd * BATCH + b]);
            int   ix = __ldcg(&g_cidx[cnd * BATCH + b]);
            if (v > best || (v == best && ix < bi)) { best = v; bi = ix; }
        }
        rv[tid] = best; ri[tid] = bi;
        __syncthreads();
        if (c8 == 0) {
            #pragma unroll
            for (int w = 1; w < 8; w++) {
                float ov = rv[tid + w]; int oi = ri[tid + w];
                if (ov > best || (ov == best && oi < bi)) { best = ov; bi = oi; }
            }
            if (mode == MODE_INT_TOK)        dout_i[b * MAXN + (MAXN - 1)] = bi;
            else if (mode == MODE_FLOAT_ALL) dout_f[b * MAXN + (MAXN - 1)] = (float)bi;
        }
    }
    if (mode != MODE_INT_TOK && cta >= 1 && cta <= BATCH) {
        const int b = cta - 1;
        const int off = (mode == MODE_FLOAT_ALL) ? (BATCH * MAXN) : 0;
        for (int k = tid; k < HDIM; k += NTHR) {
            dout_f[off + b * HDIM + k]                = __ldcg(&g_h0[0][b * HDIM + k]);
            dout_f[off + BATCH * HDIM + b * HDIM + k] = __ldcg(&g_h1[0][b * HDIM + k]);
        }
    }
}

// ---------------------------------------------------------------
extern "C" void kernel_launch(void* const* d_in, const int* in_sizes, int n_in,
                              void* d_out, int out_size)
{
    const float* h0   = (const float*)d_in[0];
    const float* emb  = (const float*)d_in[1];
    const float* Wih0 = (const float*)d_in[2];
    const float* Whh0 = (const float*)d_in[3];
    const float* bih0 = (const float*)d_in[4];
    const float* bhh0 = (const float*)d_in[5];
    const float* Wih1 = (const float*)d_in[6];
    const float* Whh1 = (const float*)d_in[7];
    const float* bih1 = (const float*)d_in[8];
    const float* bhh1 = (const float*)d_in[9];
    const float* Wout = (const float*)d_in[10];
    const float* bout = (const float*)d_in[11];

    int mode;
    if (out_size == BATCH * MAXN)          mode = MODE_INT_TOK;
    else if (out_size == 2 * BATCH * HDIM) mode = MODE_FLOAT_H;
    else                                   mode = MODE_FLOAT_ALL;

    float* dof = (float*)d_out;
    int*   doi = (int*)d_out;

    cudaFuncSetAttribute(decoder_kernel, cudaFuncAttributeMaxDynamicSharedMemorySize,
                         SMEM_BYTES);

    reset_kernel<<<(BATCH * HDIM + 511) / 512, 512>>>(h0);
    decoder_kernel<<<GRID, NTHR, SMEM_BYTES>>>(emb, Wih0, Whh0, bih0, bhh0,
                                               Wih1, Whh1, bih1, bhh1,
                                               Wout, bout, dof, doi, mode);
}